// round 6
// baseline (speedup 1.0000x reference)
#include <cuda_runtime.h>

#define NN   100000
#define EE   1600000
#define KDIM 256

// ---------------- scratch (device globals) ----------------
__device__ unsigned g_ph[(size_t)NN * 128];  // split A buffers (x, later z)
__device__ unsigned g_pl[(size_t)NN * 128];
__device__ unsigned g_rh[(size_t)NN * 128];  // split h0
__device__ unsigned g_rl[(size_t)NN * 128];
__device__ float    g_t [(size_t)NN * KDIM]; // t = h0 @ We (f32)
__device__ float    g_h1[(size_t)NN * KDIM]; // h1 (f32)
__device__ unsigned g_wdh[128 * 256], g_wdl[128 * 256];
__device__ unsigned g_weh[128 * 256], g_wel[128 * 256];
__device__ unsigned g_wch[128 * 256], g_wcl[128 * 256];
__device__ float    g_bcat[256];
__device__ float g_deg[NN];
__device__ float g_dinv[NN];
__device__ int   g_cnt[NN];
__device__ int   g_rowptr[NN + 1];
__device__ int   g_cursor[NN];
__device__ int   g_src[EE];
__device__ float g_val[EE];
__device__ int   g_is64;

// ---------------- bf16 split helper ----------------
__device__ __forceinline__ void split_pair(float x0, float x1,
                                           unsigned& hi, unsigned& lo) {
    unsigned h;
    asm("cvt.rn.bf16x2.f32 %0, %1, %2;" : "=r"(h) : "f"(x1), "f"(x0));
    float h0 = __uint_as_float(h << 16);
    float h1 = __uint_as_float(h & 0xffff0000u);
    float r0 = x0 - h0, r1 = x1 - h1;
    unsigned l;
    asm("cvt.rn.bf16x2.f32 %0, %1, %2;" : "=r"(l) : "f"(r1), "f"(r0));
    hi = h; lo = l;
}

__device__ __forceinline__ void mma16(float c[4], const unsigned a[4],
                                      unsigned b0, unsigned b1) {
    asm volatile(
        "mma.sync.aligned.m16n8k16.row.col.f32.bf16.bf16.f32 "
        "{%0,%1,%2,%3}, {%4,%5,%6,%7}, {%8,%9}, {%0,%1,%2,%3};"
        : "+f"(c[0]), "+f"(c[1]), "+f"(c[2]), "+f"(c[3])
        : "r"(a[0]), "r"(a[1]), "r"(a[2]), "r"(a[3]), "r"(b0), "r"(b1));
}

// ---------------- edge-index dtype detection ----------------
__global__ void detect_kernel(const int* __restrict__ ei32, int n_int32) {
    __shared__ int any;
    if (threadIdx.x == 0) any = 0;
    __syncthreads();
    for (int i = threadIdx.x; i < 4096; i += blockDim.x) {
        int pos = 2 * i + 1;
        if (pos < n_int32 && ei32[pos] != 0) any = 1;
    }
    __syncthreads();
    if (threadIdx.x == 0) g_is64 = (any == 0) ? 1 : 0;
}

__device__ __forceinline__ int load_idx(const void* ei, int e, int part, int i) {
    if (g_is64) return (int)((const long long*)ei)[(size_t)part * e + i];
    return ((const int*)ei)[(size_t)part * e + i];
}

// ---------------- graph preprocessing ----------------
__global__ void init_kernel(int n) {
    int i = blockIdx.x * blockDim.x + threadIdx.x;
    if (i < n) { g_deg[i] = 1.0f; g_cnt[i] = 0; }
}

__global__ void edge_pass(const void* __restrict__ ei,
                          const float* __restrict__ ew, int e) {
    int i = blockIdx.x * blockDim.x + threadIdx.x;
    if (i >= e) return;
    int c = load_idx(ei, e, 1, i);
    if ((unsigned)c >= NN) return;
    atomicAdd(&g_deg[c], ew[i]);
    atomicAdd(&g_cnt[c], 1);
}

__global__ void dinv_kernel(int n) {
    int i = blockIdx.x * blockDim.x + threadIdx.x;
    if (i < n) g_dinv[i] = rsqrtf(g_deg[i]);
}

__global__ void scan_kernel(int n) {
    __shared__ int part[1024];
    int tid = threadIdx.x;
    int chunk = (n + 1023) >> 10;
    int beg = tid * chunk;
    int end = beg + chunk; if (end > n) end = n;
    int s = 0;
    for (int i = beg; i < end; i++) s += g_cnt[i];
    part[tid] = s;
    __syncthreads();
    for (int off = 1; off < 1024; off <<= 1) {
        int v = (tid >= off) ? part[tid - off] : 0;
        __syncthreads();
        part[tid] += v;
        __syncthreads();
    }
    int run = (tid > 0) ? part[tid - 1] : 0;
    for (int i = beg; i < end; i++) {
        g_rowptr[i] = run; g_cursor[i] = run; run += g_cnt[i];
    }
    if (tid == 1023) g_rowptr[n] = part[1023];
}

__global__ void scatter_kernel(const void* __restrict__ ei,
                               const float* __restrict__ ew, int e) {
    int i = blockIdx.x * blockDim.x + threadIdx.x;
    if (i >= e) return;
    int r = load_idx(ei, e, 0, i);
    int c = load_idx(ei, e, 1, i);
    if ((unsigned)r >= NN || (unsigned)c >= NN) return;
    int pos = atomicAdd(&g_cursor[c], 1);
    g_src[pos] = r;
    g_val[pos] = ew[i] * g_dinv[r];
}

// ---------------- split kernels ----------------
// x[NN][256] f32 -> g_ph/g_pl packed k-pairs
__global__ void split_x_kernel(const float* __restrict__ src) {
    int i = blockIdx.x * blockDim.x + threadIdx.x;   // quad index (2 pairs)
    if (i >= NN * 64) return;
    float4 v = ((const float4*)src)[i];
    unsigned h0, l0, h1, l1;
    split_pair(v.x, v.y, h0, l0);
    split_pair(v.z, v.w, h1, l1);
    ((uint2*)g_ph)[i] = make_uint2(h0, h1);
    ((uint2*)g_pl)[i] = make_uint2(l0, l1);
}

// weights: W[256][ncol] -> Wh/Wl[128][256] (k-pairs). WSET 2 = concat(wm,wl) + bcat.
template<int WSET>
__global__ void split_w_kernel(const float* __restrict__ w0, const float* __restrict__ w1,
                               const float* __restrict__ b0, const float* __restrict__ b1) {
    int i = blockIdx.x * blockDim.x + threadIdx.x;
    if (i >= 128 * 256) return;
    int j = i >> 8, n = i & 255;
    float x0, x1;
    if (WSET == 2) {
        x0 = (n < 128) ? w0[(2 * j) * 128 + n]     : w1[(2 * j) * 128 + n - 128];
        x1 = (n < 128) ? w0[(2 * j + 1) * 128 + n] : w1[(2 * j + 1) * 128 + n - 128];
    } else {
        x0 = w0[(2 * j) * 256 + n];
        x1 = w0[(2 * j + 1) * 256 + n];
    }
    unsigned h, l;
    split_pair(x0, x1, h, l);
    if (WSET == 0) { g_wdh[i] = h; g_wdl[i] = l; }
    else if (WSET == 1) { g_weh[i] = h; g_wel[i] = l; }
    else { g_wch[i] = h; g_wcl[i] = l; }
    if (WSET == 2 && i < 256) g_bcat[i] = (i < 128) ? b0[i] : b1[i - 128];
}

// ---------------- TC GEMM, pre-split operands ----------------
// MODE 0: A=P, W=wd, +bias +relu, split output -> R
// MODE 1: A=R, W=we, no bias, f32 output -> g_t
// MODE 2: A=P, W=wcat, +g_bcat, split mu/logstd f32 -> Cout
template<int MODE>
__global__ __launch_bounds__(256)
void gemm_tc(const float* __restrict__ bias, float* __restrict__ Cout, int M) {
    const unsigned* Ah = (MODE == 1) ? g_rh : g_ph;
    const unsigned* Al = (MODE == 1) ? g_rl : g_pl;
    const unsigned* Wh = (MODE == 0) ? g_wdh : (MODE == 1) ? g_weh : g_wch;
    const unsigned* Wl = (MODE == 0) ? g_wdl : (MODE == 1) ? g_wel : g_wcl;

    __shared__ unsigned As_h[128][20], As_l[128][20];
    __shared__ unsigned Bs_h[16][136], Bs_l[16][136];

    int tid  = threadIdx.x;
    int lane = tid & 31, wid = tid >> 5;
    int warp_m = wid & 3, warp_n = wid >> 2;
    int bm = blockIdx.y * 128;
    int bn = blockIdx.x * 128;
    int gid = lane >> 2, tig = lane & 3;

    float acc[2][8][4];
    #pragma unroll
    for (int a = 0; a < 2; a++)
        #pragma unroll
        for (int b = 0; b < 8; b++)
            #pragma unroll
            for (int c = 0; c < 4; c++) acc[a][b][c] = 0.f;

    for (int k0h = 0; k0h < 128; k0h += 16) {   // u32 k-pair index
        #pragma unroll
        for (int jj = 0; jj < 2; jj++) {
            int id = tid + 256 * jj;
            int r = id >> 2, c4 = (id & 3) * 4;
            int gr = bm + r;
            uint4 vh = make_uint4(0u, 0u, 0u, 0u), vl = vh;
            if (gr < M) {
                vh = *(const uint4*)&Ah[(size_t)gr * 128 + k0h + c4];
                vl = *(const uint4*)&Al[(size_t)gr * 128 + k0h + c4];
            }
            *(uint4*)&As_h[r][c4] = vh;
            *(uint4*)&As_l[r][c4] = vl;
        }
        #pragma unroll
        for (int jj = 0; jj < 2; jj++) {
            int id = tid + 256 * jj;
            int r = id >> 5, c4 = (id & 31) * 4;
            *(uint4*)&Bs_h[r][c4] = *(const uint4*)&Wh[(size_t)(k0h + r) * 256 + bn + c4];
            *(uint4*)&Bs_l[r][c4] = *(const uint4*)&Wl[(size_t)(k0h + r) * 256 + bn + c4];
        }
        __syncthreads();

        #pragma unroll
        for (int kk = 0; kk < 2; kk++) {
            int kb = kk * 8;
            unsigned ah[2][4], al[2][4];
            #pragma unroll
            for (int mt = 0; mt < 2; mt++) {
                int mr = warp_m * 32 + mt * 16;
                ah[mt][0] = As_h[mr + gid][kb + tig];
                ah[mt][1] = As_h[mr + gid + 8][kb + tig];
                ah[mt][2] = As_h[mr + gid][kb + 4 + tig];
                ah[mt][3] = As_h[mr + gid + 8][kb + 4 + tig];
                al[mt][0] = As_l[mr + gid][kb + tig];
                al[mt][1] = As_l[mr + gid + 8][kb + tig];
                al[mt][2] = As_l[mr + gid][kb + 4 + tig];
                al[mt][3] = As_l[mr + gid + 8][kb + 4 + tig];
            }
            #pragma unroll
            for (int nt = 0; nt < 8; nt++) {
                int nc = warp_n * 64 + nt * 8 + gid;
                unsigned bh0 = Bs_h[kb + tig][nc], bh1 = Bs_h[kb + 4 + tig][nc];
                unsigned bl0 = Bs_l[kb + tig][nc], bl1 = Bs_l[kb + 4 + tig][nc];
                #pragma unroll
                for (int mt = 0; mt < 2; mt++) {
                    mma16(acc[mt][nt], ah[mt], bl0, bl1);   // hi*lo
                    mma16(acc[mt][nt], al[mt], bh0, bh1);   // lo*hi
                    mma16(acc[mt][nt], ah[mt], bh0, bh1);   // hi*hi
                }
            }
        }
        __syncthreads();
    }

    #pragma unroll
    for (int mt = 0; mt < 2; mt++) {
        int rr = bm + warp_m * 32 + mt * 16 + gid;
        #pragma unroll
        for (int nt = 0; nt < 8; nt++) {
            int c = bn + warp_n * 64 + nt * 8 + tig * 2;
            float v0 = acc[mt][nt][0], v1 = acc[mt][nt][1];
            float v2 = acc[mt][nt][2], v3 = acc[mt][nt][3];
            if (MODE != 1) {
                const float* bs = (MODE == 2) ? g_bcat : bias;
                float bb0 = bs[c], bb1 = bs[c + 1];
                v0 += bb0; v1 += bb1; v2 += bb0; v3 += bb1;
            }
            if (MODE == 0) {       // relu + split write to R
                v0 = fmaxf(v0, 0.f); v1 = fmaxf(v1, 0.f);
                v2 = fmaxf(v2, 0.f); v3 = fmaxf(v3, 0.f);
                int cp = c >> 1;
                unsigned h, l;
                if (rr < M) {
                    split_pair(v0, v1, h, l);
                    g_rh[(size_t)rr * 128 + cp] = h; g_rl[(size_t)rr * 128 + cp] = l;
                }
                if (rr + 8 < M) {
                    split_pair(v2, v3, h, l);
                    g_rh[(size_t)(rr + 8) * 128 + cp] = h; g_rl[(size_t)(rr + 8) * 128 + cp] = l;
                }
            } else if (MODE == 1) {  // f32 -> g_t
                if (rr < M)     *(float2*)&g_t[(size_t)rr * 256 + c]       = make_float2(v0, v1);
                if (rr + 8 < M) *(float2*)&g_t[(size_t)(rr + 8) * 256 + c] = make_float2(v2, v3);
            } else {                 // mu/logstd split f32 out
                float* base = (c < 128) ? Cout : (Cout + (size_t)NN * 128);
                int cc = (c < 128) ? c : c - 128;
                if (rr < M)     *(float2*)&base[(size_t)rr * 128 + cc]       = make_float2(v0, v1);
                if (rr + 8 < M) *(float2*)&base[(size_t)(rr + 8) * 128 + cc] = make_float2(v2, v3);
            }
        }
    }
}

// ---------------- SpMM ----------------
// PHASE 0: g_t -> g_h1 (+bias). PHASE 1: g_h1 -> split z into g_ph/g_pl.
template<int PHASE>
__global__ __launch_bounds__(256)
void spmm_kernel(const float* __restrict__ bias, int n) {
    const float* feat = (PHASE == 0) ? g_t : g_h1;
    int warp = (blockIdx.x * blockDim.x + threadIdx.x) >> 5;
    int lane = threadIdx.x & 31;
    if (warp >= n) return;
    int beg = g_rowptr[warp];
    int end = g_rowptr[warp + 1];
    const float4* f4 = (const float4*)feat;
    float4 acc0 = make_float4(0.f, 0.f, 0.f, 0.f);
    float4 acc1 = make_float4(0.f, 0.f, 0.f, 0.f);
    int e = beg;
    for (; e + 1 < end; e += 2) {
        int   r0 = g_src[e],     r1 = g_src[e + 1];
        float w0 = g_val[e],     w1 = g_val[e + 1];
        float4 a0 = f4[(size_t)r0 * 64 + lane];
        float4 b0 = f4[(size_t)r0 * 64 + 32 + lane];
        float4 a1 = f4[(size_t)r1 * 64 + lane];
        float4 b1 = f4[(size_t)r1 * 64 + 32 + lane];
        acc0.x = fmaf(w0, a0.x, acc0.x); acc0.y = fmaf(w0, a0.y, acc0.y);
        acc0.z = fmaf(w0, a0.z, acc0.z); acc0.w = fmaf(w0, a0.w, acc0.w);
        acc1.x = fmaf(w0, b0.x, acc1.x); acc1.y = fmaf(w0, b0.y, acc1.y);
        acc1.z = fmaf(w0, b0.z, acc1.z); acc1.w = fmaf(w0, b0.w, acc1.w);
        acc0.x = fmaf(w1, a1.x, acc0.x); acc0.y = fmaf(w1, a1.y, acc0.y);
        acc0.z = fmaf(w1, a1.z, acc0.z); acc0.w = fmaf(w1, a1.w, acc0.w);
        acc1.x = fmaf(w1, b1.x, acc1.x); acc1.y = fmaf(w1, b1.y, acc1.y);
        acc1.z = fmaf(w1, b1.z, acc1.z); acc1.w = fmaf(w1, b1.w, acc1.w);
    }
    if (e < end) {
        int   r = g_src[e];
        float v = g_val[e];
        float4 a = f4[(size_t)r * 64 + lane];
        float4 b = f4[(size_t)r * 64 + 32 + lane];
        acc0.x = fmaf(v, a.x, acc0.x); acc0.y = fmaf(v, a.y, acc0.y);
        acc0.z = fmaf(v, a.z, acc0.z); acc0.w = fmaf(v, a.w, acc0.w);
        acc1.x = fmaf(v, b.x, acc1.x); acc1.y = fmaf(v, b.y, acc1.y);
        acc1.z = fmaf(v, b.z, acc1.z); acc1.w = fmaf(v, b.w, acc1.w);
    }
    float di = g_dinv[warp];
    float d2 = di * di;
    float4 s0 = f4[(size_t)warp * 64 + lane];
    float4 s1 = f4[(size_t)warp * 64 + 32 + lane];
    float4 o0, o1;
    o0.x = di * acc0.x + d2 * s0.x; o0.y = di * acc0.y + d2 * s0.y;
    o0.z = di * acc0.z + d2 * s0.z; o0.w = di * acc0.w + d2 * s0.w;
    o1.x = di * acc1.x + d2 * s1.x; o1.y = di * acc1.y + d2 * s1.y;
    o1.z = di * acc1.z + d2 * s1.z; o1.w = di * acc1.w + d2 * s1.w;
    if (PHASE == 0) {
        const float4* b4 = (const float4*)bias;
        float4 c0 = b4[lane], c1 = b4[32 + lane];
        o0.x += c0.x; o0.y += c0.y; o0.z += c0.z; o0.w += c0.w;
        o1.x += c1.x; o1.y += c1.y; o1.z += c1.z; o1.w += c1.w;
        float4* out4 = (float4*)g_h1;
        out4[(size_t)warp * 64 + lane]      = o0;
        out4[(size_t)warp * 64 + 32 + lane] = o1;
    } else {
        unsigned h, l;
        size_t base = (size_t)warp * 128;
        split_pair(o0.x, o0.y, h, l); g_ph[base + 2 * lane] = h;      g_pl[base + 2 * lane] = l;
        split_pair(o0.z, o0.w, h, l); g_ph[base + 2 * lane + 1] = h;  g_pl[base + 2 * lane + 1] = l;
        split_pair(o1.x, o1.y, h, l); g_ph[base + 64 + 2 * lane] = h;     g_pl[base + 64 + 2 * lane] = l;
        split_pair(o1.z, o1.w, h, l); g_ph[base + 64 + 2 * lane + 1] = h; g_pl[base + 64 + 2 * lane + 1] = l;
    }
}

// ---------------- launch ----------------
extern "C" void kernel_launch(void* const* d_in, const int* in_sizes, int n_in,
                              void* d_out, int out_size) {
    const float* x  = (const float*)d_in[0];
    const void*  ei = d_in[1];
    const float* ew = (const float*)d_in[2];
    const float* wd = (const float*)d_in[3];
    const float* bd = (const float*)d_in[4];
    const float* we = (const float*)d_in[5];
    const float* be = (const float*)d_in[6];
    const float* wm = (const float*)d_in[7];
    const float* bmu = (const float*)d_in[8];
    const float* wl = (const float*)d_in[9];
    const float* bl = (const float*)d_in[10];
    float* out = (float*)d_out;

    const int n = NN;
    const int e = EE;

    detect_kernel<<<1, 1024>>>((const int*)ei, 2 * e);
    init_kernel<<<(n + 255) / 256, 256>>>(n);
    edge_pass<<<(e + 255) / 256, 256>>>(ei, ew, e);
    dinv_kernel<<<(n + 255) / 256, 256>>>(n);
    scan_kernel<<<1, 1024>>>(n);
    scatter_kernel<<<(e + 255) / 256, 256>>>(ei, ew, e);

    split_w_kernel<0><<<128, 256>>>(wd, nullptr, nullptr, nullptr);
    split_w_kernel<1><<<128, 256>>>(we, nullptr, nullptr, nullptr);
    split_w_kernel<2><<<128, 256>>>(wm, wl, bmu, bl);
    split_x_kernel<<<(NN * 64 + 255) / 256, 256>>>(x);

    dim3 grid(2, (n + 127) / 128);
    int spmm_blocks = (n * 32 + 255) / 256;

    gemm_tc<0><<<grid, 256>>>(bd, nullptr, n);        // h0 split -> R
    gemm_tc<1><<<grid, 256>>>(nullptr, nullptr, n);   // t f32 -> g_t
    spmm_kernel<0><<<spmm_blocks, 256>>>(be, n);      // h1 -> g_h1
    spmm_kernel<1><<<spmm_blocks, 256>>>(nullptr, n); // z split -> P
    gemm_tc<2><<<grid, 256>>>(nullptr, out, n);       // mu/logstd
}